// round 3
// baseline (speedup 1.0000x reference)
#include <cuda_runtime.h>
#include <cstdint>

#define HW      262144          // 512*512 = 2^18
#define BSZ     64
#define CC      3
#define NU      (BSZ*HW)        // 16777216 uniforms (mask domain)
#define NX      (BSZ*CC*HW)     // 50331648 x elements
#define KKEEP   183500          // int(262144*0.7)
#define CAP     1024
#define SEG     32              // histogram blocks per row

// ---------------- static device scratch (no allocation allowed) -------------
__device__ uint32_t           g_m[NU];               // cached 23-bit uniform keys
__device__ uint32_t           g_hist[BSZ][2048];
__device__ uint32_t           g_bucket[BSZ];
__device__ uint32_t           g_rank[BSZ];           // 1-indexed rank within bucket
__device__ unsigned long long g_pairs[BSZ][CAP];
__device__ uint32_t           g_cnt[BSZ];
__device__ uint32_t           g_thresh[BSZ];
__device__ uint32_t           g_tiecols[BSZ][64];
__device__ uint32_t           g_ntk[BSZ];

// ---------------- Threefry-2x32 (20 rounds), matches jax._src.prng ----------
__host__ __device__ __forceinline__
void tf2x32(uint32_t k0, uint32_t k1, uint32_t x0, uint32_t x1,
            uint32_t &o0, uint32_t &o1) {
    uint32_t ks2 = k0 ^ k1 ^ 0x1BD11BDAu;
#define TFR(r) { x0 += x1; x1 = (x1 << (r)) | (x1 >> (32 - (r))); x1 ^= x0; }
    x0 += k0;  x1 += k1;
    TFR(13) TFR(15) TFR(26) TFR(6)
    x0 += k1;  x1 += ks2 + 1u;
    TFR(17) TFR(29) TFR(16) TFR(24)
    x0 += ks2; x1 += k0 + 2u;
    TFR(13) TFR(15) TFR(26) TFR(6)
    x0 += k0;  x1 += k1 + 3u;
    TFR(17) TFR(29) TFR(16) TFR(24)
    x0 += k1;  x1 += ks2 + 4u;
    TFR(13) TFR(15) TFR(26) TFR(6)
    x0 += ks2; x1 += k0 + 5u;
#undef TFR
    o0 = x0; o1 = x1;
}

// jax_threefry_partitionable=True 32-bit random bits: ctr=(0,i), out = x0^x1
__device__ __forceinline__ uint32_t rbits32(uint32_t k0, uint32_t k1, uint32_t i) {
    uint32_t a, b;
    tf2x32(k0, k1, 0u, i, a, b);
    return a ^ b;
}

// XLA ErfInv (fp32, Giles polynomial)
__device__ __forceinline__ float erfinv_f(float x) {
    float w = -__logf((1.0f - x) * (1.0f + x));
    float p;
    if (w < 5.0f) {
        w -= 2.5f;
        p =               2.81022636e-08f;
        p = fmaf(p, w,    3.43273939e-07f);
        p = fmaf(p, w,   -3.5233877e-06f);
        p = fmaf(p, w,   -4.39150654e-06f);
        p = fmaf(p, w,    0.00021858087f);
        p = fmaf(p, w,   -0.00125372503f);
        p = fmaf(p, w,   -0.00417768164f);
        p = fmaf(p, w,    0.246640727f);
        p = fmaf(p, w,    1.50140941f);
    } else {
        w = sqrtf(w) - 3.0f;
        p =              -0.000200214257f;
        p = fmaf(p, w,    0.000100950558f);
        p = fmaf(p, w,    0.00134934322f);
        p = fmaf(p, w,   -0.00367342844f);
        p = fmaf(p, w,    0.00573950773f);
        p = fmaf(p, w,   -0.0076224613f);
        p = fmaf(p, w,    0.00943887047f);
        p = fmaf(p, w,    1.00167406f);
        p = fmaf(p, w,    2.83297682f);
    }
    return p * x;
}

// ---------------- kernels ----------------------------------------------------
__global__ void k_init() {
    uint32_t i = blockIdx.x * blockDim.x + threadIdx.x;
    if (i < BSZ * 2048) ((uint32_t*)g_hist)[i] = 0u;
    if (i < BSZ) { g_cnt[i] = 0u; g_ntk[i] = 0u; }
}

// Generate uniforms, cache m=bits>>9, per-row 2048-bucket histogram (top 11 bits)
__global__ void k_hist(uint32_t mk0, uint32_t mk1) {
    __shared__ uint32_t sh[2048];
    for (int j = threadIdx.x; j < 2048; j += 256) sh[j] = 0u;
    __syncthreads();
    uint32_t row  = blockIdx.x / SEG;
    uint32_t seg  = blockIdx.x % SEG;
    uint32_t base = row * HW + seg * (HW / SEG);
#pragma unroll 4
    for (int it = 0; it < (HW / SEG) / 256; it++) {
        uint32_t i    = base + it * 256 + threadIdx.x;
        uint32_t m    = rbits32(mk0, mk1, i) >> 9;
        g_m[i] = m;
        atomicAdd(&sh[m >> 12], 1u);
    }
    __syncthreads();
    for (int j = threadIdx.x; j < 2048; j += 256)
        if (sh[j]) atomicAdd(&g_hist[row][j], sh[j]);
}

__global__ void k_scan() {
    int row = threadIdx.x;
    if (row >= BSZ) return;
    uint32_t cum = 0;
    for (int b = 0; b < 2048; b++) {
        uint32_t h = g_hist[row][b];
        if (cum + h >= (uint32_t)KKEEP) {
            g_bucket[row] = (uint32_t)b;
            g_rank[row]   = (uint32_t)KKEEP - cum;   // 1-indexed within bucket
            return;
        }
        cum += h;
    }
}

__global__ void k_collect() {
    uint32_t i   = blockIdx.x * blockDim.x + threadIdx.x;
    uint32_t m   = g_m[i];
    uint32_t row = i >> 18;
    if ((m >> 12) == g_bucket[row]) {
        uint32_t pos = atomicAdd(&g_cnt[row], 1u);
        if (pos < CAP)
            g_pairs[row][pos] = (((unsigned long long)m) << 18) | (i & 0x3FFFFu);
    }
}

// One block per row: exact k-th element + stable (index-ordered) tie set
__global__ void k_resolve() {
    int row = blockIdx.x;
    uint32_t n = min(g_cnt[row], (uint32_t)CAP);
    __shared__ unsigned long long sp[CAP];
    __shared__ uint32_t sT;
    for (uint32_t j = threadIdx.x; j < n; j += blockDim.x) sp[j] = g_pairs[row][j];
    __syncthreads();
    uint32_t selr = g_rank[row];
    for (uint32_t j = threadIdx.x; j < n; j += blockDim.x) {
        unsigned long long v = sp[j];
        uint32_t r = 0;
        for (uint32_t l = 0; l < n; l++) r += (sp[l] < v);
        if (r == selr - 1u) { sT = (uint32_t)(v >> 18); g_thresh[row] = sT; }
    }
    __syncthreads();
    uint32_t T = sT;
    for (uint32_t j = threadIdx.x; j < n; j += blockDim.x) {
        unsigned long long v = sp[j];
        if ((uint32_t)(v >> 18) == T) {
            uint32_t r = 0;
            for (uint32_t l = 0; l < n; l++) r += (sp[l] < v);
            if (r < selr) {
                uint32_t pos = atomicAdd(&g_ntk[row], 1u);
                if (pos < 64u) g_tiecols[row][pos] = (uint32_t)(v & 0x3FFFFu);
            }
        }
    }
}

__global__ void k_mask(float* __restrict__ maskout) {
    uint32_t i   = blockIdx.x * blockDim.x + threadIdx.x;
    uint32_t m   = g_m[i];
    uint32_t row = i >> 18;
    uint32_t T   = g_thresh[row];
    bool keep = (m < T);
    if (m == T) {
        uint32_t col = i & 0x3FFFFu;
        uint32_t ntk = g_ntk[row];
        for (uint32_t j = 0; j < ntk; j++)
            if (g_tiecols[row][j] == col) keep = true;
    }
    maskout[i] = keep ? 1.0f : 0.0f;
}

// out = x * mask * (normal*0.1 + 1), vectorized by 4
__global__ void k_outx(const float4* __restrict__ x, const float4* __restrict__ maskv,
                       float4* __restrict__ out, uint32_t nk0, uint32_t nk1) {
    uint32_t v = blockIdx.x * blockDim.x + threadIdx.x;   // [0, NX/4)
    uint32_t g = v * 4u;
    uint32_t bc = g >> 18;        // b*3 + c
    uint32_t b  = bc / 3u;
    uint32_t p  = g & 0x3FFFFu;
    float4 xv = x[v];
    float4 mv = maskv[(b * HW + p) >> 2];
    float ns[4];
#pragma unroll
    for (int j = 0; j < 4; j++) {
        uint32_t bits = rbits32(nk0, nk1, g + (uint32_t)j);
        float f = __uint_as_float((bits >> 9) | 0x3F800000u) - 1.0f;
        float u = f * 2.0f + (-0.99999994f);      // lo = nextafter(-1,0), hi-lo = 2
        u = fmaxf(u, -0.99999994f);
        float nrm = 1.4142135623730951f * erfinv_f(u);
        ns[j] = fmaf(nrm, 0.1f, 1.0f);
    }
    float4 o;
    o.x = xv.x * mv.x * ns[0];
    o.y = xv.y * mv.y * ns[1];
    o.z = xv.z * mv.z * ns[2];
    o.w = xv.w * mv.w * ns[3];
    out[v] = o;
}

// ---------------- launch ------------------------------------------------------
extern "C" void kernel_launch(void* const* d_in, const int* in_sizes, int n_in,
                              void* d_out, int out_size) {
    const float* x   = (const float*)d_in[0];
    float* out       = (float*)d_out;
    float* maskout   = out + NX;          // output layout: [x (NX) | mask (NU)]

    // jax.random.key(42) -> (0,42); partitionable fold-like split:
    uint32_t mk0, mk1, nk0, nk1;
    tf2x32(0u, 42u, 0u, 0u, mk0, mk1);    // k_mask
    tf2x32(0u, 42u, 0u, 1u, nk0, nk1);    // k_noise

    k_init   <<<512, 256>>>();
    k_hist   <<<BSZ * SEG, 256>>>(mk0, mk1);
    k_scan   <<<1, 64>>>();
    k_collect<<<NU / 256, 256>>>();
    k_resolve<<<BSZ, 256>>>();
    k_mask   <<<NU / 256, 256>>>(maskout);
    k_outx   <<<(NX / 4) / 256, 256>>>((const float4*)x, (const float4*)maskout,
                                       (float4*)out, nk0, nk1);
}

// round 6
// speedup vs baseline: 1.2214x; 1.2214x over previous
#include <cuda_runtime.h>
#include <cstdint>

#define HW      262144          // 512*512 = 2^18
#define BSZ     64
#define CC      3
#define NU      (BSZ*HW)        // 16777216 uniforms (mask domain)
#define NX      (BSZ*CC*HW)     // 50331648 x elements
#define KKEEP   183500          // int(262144*0.7)
#define CAP     1024
#define SEG     32              // histogram blocks per row

// ---------------- static device scratch (no allocation allowed) -------------
__device__ uint32_t           g_m[NU];               // cached 23-bit uniform keys
__device__ uint32_t           g_hist[BSZ][2048];
__device__ uint32_t           g_bucket[BSZ];
__device__ uint32_t           g_rank[BSZ];           // 1-indexed rank within bucket
__device__ unsigned long long g_pairs[BSZ][CAP];
__device__ uint32_t           g_cnt[BSZ];
__device__ uint32_t           g_thresh[BSZ];
__device__ uint32_t           g_tiecols[BSZ][64];
__device__ uint32_t           g_ntk[BSZ];

// ---------------- Threefry-2x32 (20 rounds), matches jax._src.prng ----------
__host__ __device__ __forceinline__
void tf2x32(uint32_t k0, uint32_t k1, uint32_t x0, uint32_t x1,
            uint32_t &o0, uint32_t &o1) {
    uint32_t ks2 = k0 ^ k1 ^ 0x1BD11BDAu;
#define TFR(r) { x0 += x1; x1 = (x1 << (r)) | (x1 >> (32 - (r))); x1 ^= x0; }
    x0 += k0;  x1 += k1;
    TFR(13) TFR(15) TFR(26) TFR(6)
    x0 += k1;  x1 += ks2 + 1u;
    TFR(17) TFR(29) TFR(16) TFR(24)
    x0 += ks2; x1 += k0 + 2u;
    TFR(13) TFR(15) TFR(26) TFR(6)
    x0 += k0;  x1 += k1 + 3u;
    TFR(17) TFR(29) TFR(16) TFR(24)
    x0 += k1;  x1 += ks2 + 4u;
    TFR(13) TFR(15) TFR(26) TFR(6)
    x0 += ks2; x1 += k0 + 5u;
#undef TFR
    o0 = x0; o1 = x1;
}

// jax_threefry_partitionable=True 32-bit random bits: ctr=(0,i), out = x0^x1
__device__ __forceinline__ uint32_t rbits32(uint32_t k0, uint32_t k1, uint32_t i) {
    uint32_t a, b;
    tf2x32(k0, k1, 0u, i, a, b);
    return a ^ b;
}

// XLA ErfInv (fp32, Giles polynomial)
__device__ __forceinline__ float erfinv_f(float x) {
    float w = -__logf((1.0f - x) * (1.0f + x));
    float p;
    if (w < 5.0f) {
        w -= 2.5f;
        p =               2.81022636e-08f;
        p = fmaf(p, w,    3.43273939e-07f);
        p = fmaf(p, w,   -3.5233877e-06f);
        p = fmaf(p, w,   -4.39150654e-06f);
        p = fmaf(p, w,    0.00021858087f);
        p = fmaf(p, w,   -0.00125372503f);
        p = fmaf(p, w,   -0.00417768164f);
        p = fmaf(p, w,    0.246640727f);
        p = fmaf(p, w,    1.50140941f);
    } else {
        w = sqrtf(w) - 3.0f;
        p =              -0.000200214257f;
        p = fmaf(p, w,    0.000100950558f);
        p = fmaf(p, w,    0.00134934322f);
        p = fmaf(p, w,   -0.00367342844f);
        p = fmaf(p, w,    0.00573950773f);
        p = fmaf(p, w,   -0.0076224613f);
        p = fmaf(p, w,    0.00943887047f);
        p = fmaf(p, w,    1.00167406f);
        p = fmaf(p, w,    2.83297682f);
    }
    return p * x;
}

// noise factor for element index gi: 1 + 0.1 * N(0,1)
__device__ __forceinline__ float noise_f(uint32_t nk0, uint32_t nk1, uint32_t gi) {
    uint32_t bits = rbits32(nk0, nk1, gi);
    float f = __uint_as_float((bits >> 9) | 0x3F800000u) - 1.0f;
    float u = f * 2.0f + (-0.99999994f);      // lo = nextafter(-1,0), hi-lo = 2
    u = fmaxf(u, -0.99999994f);
    float nrm = 1.4142135623730951f * erfinv_f(u);
    return fmaf(nrm, 0.1f, 1.0f);
}

// ---------------- kernels ----------------------------------------------------
__global__ void k_init() {
    uint32_t i = blockIdx.x * blockDim.x + threadIdx.x;
    if (i < BSZ * 2048) ((uint32_t*)g_hist)[i] = 0u;
    if (i < BSZ) { g_cnt[i] = 0u; g_ntk[i] = 0u; }
}

// Generate uniforms, cache m=bits>>9, per-row 2048-bucket histogram (top 11 bits)
__global__ void k_hist(uint32_t mk0, uint32_t mk1) {
    __shared__ uint32_t sh[2048];
    for (int j = threadIdx.x; j < 2048; j += 256) sh[j] = 0u;
    __syncthreads();
    uint32_t row  = blockIdx.x / SEG;
    uint32_t seg  = blockIdx.x % SEG;
    uint32_t base = row * HW + seg * (HW / SEG);
#pragma unroll 8
    for (int it = 0; it < (HW / SEG) / 256; it++) {
        uint32_t i    = base + it * 256 + threadIdx.x;
        uint32_t m    = rbits32(mk0, mk1, i) >> 9;
        g_m[i] = m;
        atomicAdd(&sh[m >> 12], 1u);
    }
    __syncthreads();
    for (int j = threadIdx.x; j < 2048; j += 256)
        if (sh[j]) atomicAdd(&g_hist[row][j], sh[j]);
}

__global__ void k_scan() {
    int row = threadIdx.x;
    if (row >= BSZ) return;
    uint32_t cum = 0;
    for (int b = 0; b < 2048; b++) {
        uint32_t h = g_hist[row][b];
        if (cum + h >= (uint32_t)KKEEP) {
            g_bucket[row] = (uint32_t)b;
            g_rank[row]   = (uint32_t)KKEEP - cum;   // 1-indexed within bucket
            return;
        }
        cum += h;
    }
}

// vectorized: 4 keys per thread via uint4
__global__ void k_collect() {
    uint32_t q = blockIdx.x * blockDim.x + threadIdx.x;   // [0, NU/4)
    uint32_t i0  = q * 4u;
    uint32_t row = i0 >> 18;
    uint32_t bk  = g_bucket[row];
    uint4 mv = reinterpret_cast<const uint4*>(g_m)[q];
    uint32_t ms[4] = {mv.x, mv.y, mv.z, mv.w};
#pragma unroll
    for (int j = 0; j < 4; j++) {
        if ((ms[j] >> 12) == bk) {
            uint32_t pos = atomicAdd(&g_cnt[row], 1u);
            if (pos < CAP)
                g_pairs[row][pos] =
                    (((unsigned long long)ms[j]) << 18) | ((i0 + j) & 0x3FFFFu);
        }
    }
}

// One block per row: exact k-th element + stable (index-ordered) tie set
__global__ void k_resolve() {
    int row = blockIdx.x;
    uint32_t n = min(g_cnt[row], (uint32_t)CAP);
    __shared__ unsigned long long sp[CAP];
    __shared__ uint32_t sT;
    for (uint32_t j = threadIdx.x; j < n; j += blockDim.x) sp[j] = g_pairs[row][j];
    __syncthreads();
    uint32_t selr = g_rank[row];
    for (uint32_t j = threadIdx.x; j < n; j += blockDim.x) {
        unsigned long long v = sp[j];
        uint32_t r = 0;
        for (uint32_t l = 0; l < n; l++) r += (sp[l] < v);
        if (r == selr - 1u) { sT = (uint32_t)(v >> 18); g_thresh[row] = sT; }
    }
    __syncthreads();
    uint32_t T = sT;
    for (uint32_t j = threadIdx.x; j < n; j += blockDim.x) {
        unsigned long long v = sp[j];
        if ((uint32_t)(v >> 18) == T) {
            uint32_t r = 0;
            for (uint32_t l = 0; l < n; l++) r += (sp[l] < v);
            if (r < selr) {
                uint32_t pos = atomicAdd(&g_ntk[row], 1u);
                if (pos < 64u) g_tiecols[row][pos] = (uint32_t)(v & 0x3FFFFu);
            }
        }
    }
}

// Fused: per pixel-quad -> mask (write) + all 3 channels of out
__global__ void __launch_bounds__(256)
k_out_fused(const float4* __restrict__ x, float4* __restrict__ out,
            float4* __restrict__ maskout, uint32_t nk0, uint32_t nk1) {
    uint32_t q   = blockIdx.x * blockDim.x + threadIdx.x;  // [0, NU/4)
    uint32_t pix = q * 4u;
    uint32_t b   = pix >> 18;
    uint32_t p   = pix & 0x3FFFFu;
    uint32_t T   = g_thresh[b];

    uint4 mq = reinterpret_cast<const uint4*>(g_m)[q];
    uint32_t ms[4] = {mq.x, mq.y, mq.z, mq.w};
    float mk[4];
    // common fast path: no element in this quad ties with T
    bool anytie = (ms[0] == T) | (ms[1] == T) | (ms[2] == T) | (ms[3] == T);
#pragma unroll
    for (int j = 0; j < 4; j++) mk[j] = (ms[j] < T) ? 1.0f : 0.0f;
    if (anytie) {
        uint32_t ntk = g_ntk[b];
#pragma unroll
        for (int j = 0; j < 4; j++) {
            if (ms[j] == T) {
                uint32_t col = p + (uint32_t)j;
                for (uint32_t t = 0; t < ntk; t++)
                    if (g_tiecols[b][t] == col) mk[j] = 1.0f;
            }
        }
    }
    maskout[q] = make_float4(mk[0], mk[1], mk[2], mk[3]);

    uint32_t gibase = (b * 3u) * (uint32_t)HW + p;   // channel 0 element index
#pragma unroll
    for (int c = 0; c < 3; c++) {
        uint32_t gi = gibase + (uint32_t)c * (uint32_t)HW;
        float4 xv = x[gi >> 2];
        float n0 = noise_f(nk0, nk1, gi + 0u);
        float n1 = noise_f(nk0, nk1, gi + 1u);
        float n2 = noise_f(nk0, nk1, gi + 2u);
        float n3 = noise_f(nk0, nk1, gi + 3u);
        float4 o;
        o.x = xv.x * mk[0] * n0;
        o.y = xv.y * mk[1] * n1;
        o.z = xv.z * mk[2] * n2;
        o.w = xv.w * mk[3] * n3;
        out[gi >> 2] = o;
    }
}

// ---------------- launch ------------------------------------------------------
extern "C" void kernel_launch(void* const* d_in, const int* in_sizes, int n_in,
                              void* d_out, int out_size) {
    const float* x   = (const float*)d_in[0];
    float* out       = (float*)d_out;
    float* maskout   = out + NX;          // output layout: [x (NX) | mask (NU)]

    // jax.random.key(42) -> (0,42); partitionable fold-like split:
    uint32_t mk0, mk1, nk0, nk1;
    tf2x32(0u, 42u, 0u, 0u, mk0, mk1);    // k_mask
    tf2x32(0u, 42u, 0u, 1u, nk0, nk1);    // k_noise

    k_init     <<<512, 256>>>();
    k_hist     <<<BSZ * SEG, 256>>>(mk0, mk1);
    k_scan     <<<1, 64>>>();
    k_collect  <<<(NU / 4) / 256, 256>>>();
    k_resolve  <<<BSZ, 256>>>();
    k_out_fused<<<(NU / 4) / 256, 256>>>((const float4*)x, (float4*)out,
                                         (float4*)maskout, nk0, nk1);
}

// round 9
// speedup vs baseline: 1.2288x; 1.0060x over previous
#include <cuda_runtime.h>
#include <cstdint>

#define HW      262144          // 512*512 = 2^18
#define BSZ     64
#define CC      3
#define NU      (BSZ*HW)        // 16777216 uniforms (mask domain)
#define NX      (BSZ*CC*HW)     // 50331648 x elements
#define KKEEP   183500          // int(262144*0.7)
#define CAP     1024
#define SEG     32              // histogram blocks per row

// ---------------- static device scratch (no allocation allowed) -------------
__device__ uint32_t           g_m[NU];               // cached 23-bit uniform keys
__device__ uint32_t           g_hist[BSZ][2048];
__device__ uint32_t           g_bucket[BSZ];
__device__ uint32_t           g_rank[BSZ];           // 1-indexed rank within bucket
__device__ unsigned long long g_pairs[BSZ][CAP];
__device__ uint32_t           g_cnt[BSZ];
__device__ uint32_t           g_thresh[BSZ];
__device__ uint32_t           g_tiecols[BSZ][64];
__device__ uint32_t           g_ntk[BSZ];

// ---------------- Threefry-2x32 (20 rounds), matches jax._src.prng ----------
// Two rotate forms:
//  TFR_S: SHF.L (alu pipe) + LOP3 (alu)            -> 2 alu
//  TFR_I: IMAD.WIDE.U32 (fma pipe) + LOP3(lo,hi,x0) -> 1 fma + 1 alu
// Mixing them balances the fma/alu pipes per kernel.
#define TFR_S(r) { x0 += x1; x1 = ((x1 << (r)) | (x1 >> (32 - (r)))) ^ x0; }
#define TFR_I(r) { x0 += x1;                                                 \
                   unsigned long long _p = (unsigned long long)x1 *          \
                                           (uint32_t)(1u << (r));            \
                   x1 = ((uint32_t)_p | (uint32_t)(_p >> 32)) ^ x0; }

// all-IMAD rotations: for integer-only callers (mask/hist path)
__host__ __device__ __forceinline__
void tf2x32_i(uint32_t k0, uint32_t k1, uint32_t x0, uint32_t x1,
              uint32_t &o0, uint32_t &o1) {
    uint32_t ks2 = k0 ^ k1 ^ 0x1BD11BDAu;
    x0 += k0;  x1 += k1;
    TFR_I(13) TFR_I(15) TFR_I(26) TFR_I(6)
    x0 += k1;  x1 += ks2 + 1u;
    TFR_I(17) TFR_I(29) TFR_I(16) TFR_I(24)
    x0 += ks2; x1 += k0 + 2u;
    TFR_I(13) TFR_I(15) TFR_I(26) TFR_I(6)
    x0 += k0;  x1 += k1 + 3u;
    TFR_I(17) TFR_I(29) TFR_I(16) TFR_I(24)
    x0 += k1;  x1 += ks2 + 4u;
    TFR_I(13) TFR_I(15) TFR_I(26) TFR_I(6)
    x0 += ks2; x1 += k0 + 5u;
    o0 = x0; o1 = x1;
}

// mixed rotations (10 IMAD / 10 SHF): for the noise path, whose erfinv FFMA
// chain already loads the fma pipe
__device__ __forceinline__
void tf2x32_m(uint32_t k0, uint32_t k1, uint32_t x0, uint32_t x1,
              uint32_t &o0, uint32_t &o1) {
    uint32_t ks2 = k0 ^ k1 ^ 0x1BD11BDAu;
    x0 += k0;  x1 += k1;
    TFR_I(13) TFR_S(15) TFR_I(26) TFR_S(6)
    x0 += k1;  x1 += ks2 + 1u;
    TFR_I(17) TFR_S(29) TFR_I(16) TFR_S(24)
    x0 += ks2; x1 += k0 + 2u;
    TFR_I(13) TFR_S(15) TFR_I(26) TFR_S(6)
    x0 += k0;  x1 += k1 + 3u;
    TFR_I(17) TFR_S(29) TFR_I(16) TFR_S(24)
    x0 += k1;  x1 += ks2 + 4u;
    TFR_I(13) TFR_S(15) TFR_I(26) TFR_S(6)
    x0 += ks2; x1 += k0 + 5u;
    o0 = x0; o1 = x1;
}

// jax_threefry_partitionable=True 32-bit random bits: ctr=(0,i), out = x0^x1
__device__ __forceinline__ uint32_t rbits32_i(uint32_t k0, uint32_t k1, uint32_t i) {
    uint32_t a, b;
    tf2x32_i(k0, k1, 0u, i, a, b);
    return a ^ b;
}
__device__ __forceinline__ uint32_t rbits32_m(uint32_t k0, uint32_t k1, uint32_t i) {
    uint32_t a, b;
    tf2x32_m(k0, k1, 0u, i, a, b);
    return a ^ b;
}

// XLA ErfInv (fp32, Giles polynomial)
__device__ __forceinline__ float erfinv_f(float x) {
    float w = -__logf((1.0f - x) * (1.0f + x));
    float p;
    if (w < 5.0f) {
        w -= 2.5f;
        p =               2.81022636e-08f;
        p = fmaf(p, w,    3.43273939e-07f);
        p = fmaf(p, w,   -3.5233877e-06f);
        p = fmaf(p, w,   -4.39150654e-06f);
        p = fmaf(p, w,    0.00021858087f);
        p = fmaf(p, w,   -0.00125372503f);
        p = fmaf(p, w,   -0.00417768164f);
        p = fmaf(p, w,    0.246640727f);
        p = fmaf(p, w,    1.50140941f);
    } else {
        w = sqrtf(w) - 3.0f;
        p =              -0.000200214257f;
        p = fmaf(p, w,    0.000100950558f);
        p = fmaf(p, w,    0.00134934322f);
        p = fmaf(p, w,   -0.00367342844f);
        p = fmaf(p, w,    0.00573950773f);
        p = fmaf(p, w,   -0.0076224613f);
        p = fmaf(p, w,    0.00943887047f);
        p = fmaf(p, w,    1.00167406f);
        p = fmaf(p, w,    2.83297682f);
    }
    return p * x;
}

// noise factor for element index gi: 1 + 0.1 * N(0,1)
__device__ __forceinline__ float noise_f(uint32_t nk0, uint32_t nk1, uint32_t gi) {
    uint32_t bits = rbits32_m(nk0, nk1, gi);
    float f = __uint_as_float((bits >> 9) | 0x3F800000u) - 1.0f;
    float u = f * 2.0f + (-0.99999994f);      // lo = nextafter(-1,0), hi-lo = 2
    u = fmaxf(u, -0.99999994f);
    float nrm = 1.4142135623730951f * erfinv_f(u);
    return fmaf(nrm, 0.1f, 1.0f);
}

// ---------------- kernels ----------------------------------------------------
__global__ void k_init() {
    uint32_t i = blockIdx.x * blockDim.x + threadIdx.x;
    if (i < BSZ * 2048) ((uint32_t*)g_hist)[i] = 0u;
    if (i < BSZ) { g_cnt[i] = 0u; g_ntk[i] = 0u; }
}

// Generate uniforms, cache m=bits>>9, per-row 2048-bucket histogram (top 11 bits)
__global__ void k_hist(uint32_t mk0, uint32_t mk1) {
    __shared__ uint32_t sh[2048];
    for (int j = threadIdx.x; j < 2048; j += 256) sh[j] = 0u;
    __syncthreads();
    uint32_t row  = blockIdx.x / SEG;
    uint32_t seg  = blockIdx.x % SEG;
    uint32_t base = row * HW + seg * (HW / SEG);
#pragma unroll 8
    for (int it = 0; it < (HW / SEG) / 256; it++) {
        uint32_t i    = base + it * 256 + threadIdx.x;
        uint32_t m    = rbits32_i(mk0, mk1, i) >> 9;
        g_m[i] = m;
        atomicAdd(&sh[m >> 12], 1u);
    }
    __syncthreads();
    for (int j = threadIdx.x; j < 2048; j += 256)
        if (sh[j]) atomicAdd(&g_hist[row][j], sh[j]);
}

__global__ void k_scan() {
    int row = threadIdx.x;
    if (row >= BSZ) return;
    uint32_t cum = 0;
    for (int b = 0; b < 2048; b++) {
        uint32_t h = g_hist[row][b];
        if (cum + h >= (uint32_t)KKEEP) {
            g_bucket[row] = (uint32_t)b;
            g_rank[row]   = (uint32_t)KKEEP - cum;   // 1-indexed within bucket
            return;
        }
        cum += h;
    }
}

// vectorized: 4 keys per thread via uint4
__global__ void k_collect() {
    uint32_t q = blockIdx.x * blockDim.x + threadIdx.x;   // [0, NU/4)
    uint32_t i0  = q * 4u;
    uint32_t row = i0 >> 18;
    uint32_t bk  = g_bucket[row];
    uint4 mv = reinterpret_cast<const uint4*>(g_m)[q];
    uint32_t ms[4] = {mv.x, mv.y, mv.z, mv.w};
#pragma unroll
    for (int j = 0; j < 4; j++) {
        if ((ms[j] >> 12) == bk) {
            uint32_t pos = atomicAdd(&g_cnt[row], 1u);
            if (pos < CAP)
                g_pairs[row][pos] =
                    (((unsigned long long)ms[j]) << 18) | ((i0 + j) & 0x3FFFFu);
        }
    }
}

// One block per row: exact k-th element + stable (index-ordered) tie set
__global__ void k_resolve() {
    int row = blockIdx.x;
    uint32_t n = min(g_cnt[row], (uint32_t)CAP);
    __shared__ unsigned long long sp[CAP];
    __shared__ uint32_t sT;
    for (uint32_t j = threadIdx.x; j < n; j += blockDim.x) sp[j] = g_pairs[row][j];
    __syncthreads();
    uint32_t selr = g_rank[row];
    for (uint32_t j = threadIdx.x; j < n; j += blockDim.x) {
        unsigned long long v = sp[j];
        uint32_t r = 0;
        for (uint32_t l = 0; l < n; l++) r += (sp[l] < v);
        if (r == selr - 1u) { sT = (uint32_t)(v >> 18); g_thresh[row] = sT; }
    }
    __syncthreads();
    uint32_t T = sT;
    for (uint32_t j = threadIdx.x; j < n; j += blockDim.x) {
        unsigned long long v = sp[j];
        if ((uint32_t)(v >> 18) == T) {
            uint32_t r = 0;
            for (uint32_t l = 0; l < n; l++) r += (sp[l] < v);
            if (r < selr) {
                uint32_t pos = atomicAdd(&g_ntk[row], 1u);
                if (pos < 64u) g_tiecols[row][pos] = (uint32_t)(v & 0x3FFFFu);
            }
        }
    }
}

// Fused: per pixel-quad -> mask (write) + all 3 channels of out
__global__ void __launch_bounds__(256)
k_out_fused(const float4* __restrict__ x, float4* __restrict__ out,
            float4* __restrict__ maskout, uint32_t nk0, uint32_t nk1) {
    uint32_t q   = blockIdx.x * blockDim.x + threadIdx.x;  // [0, NU/4)
    uint32_t pix = q * 4u;
    uint32_t b   = pix >> 18;
    uint32_t p   = pix & 0x3FFFFu;
    uint32_t T   = g_thresh[b];

    uint4 mq = reinterpret_cast<const uint4*>(g_m)[q];
    uint32_t ms[4] = {mq.x, mq.y, mq.z, mq.w};
    float mk[4];
    // common fast path: no element in this quad ties with T
    bool anytie = (ms[0] == T) | (ms[1] == T) | (ms[2] == T) | (ms[3] == T);
#pragma unroll
    for (int j = 0; j < 4; j++) mk[j] = (ms[j] < T) ? 1.0f : 0.0f;
    if (anytie) {
        uint32_t ntk = g_ntk[b];
#pragma unroll
        for (int j = 0; j < 4; j++) {
            if (ms[j] == T) {
                uint32_t col = p + (uint32_t)j;
                for (uint32_t t = 0; t < ntk; t++)
                    if (g_tiecols[b][t] == col) mk[j] = 1.0f;
            }
        }
    }
    maskout[q] = make_float4(mk[0], mk[1], mk[2], mk[3]);

    uint32_t gibase = (b * 3u) * (uint32_t)HW + p;   // channel 0 element index
#pragma unroll
    for (int c = 0; c < 3; c++) {
        uint32_t gi = gibase + (uint32_t)c * (uint32_t)HW;
        float4 xv = x[gi >> 2];
        float n0 = noise_f(nk0, nk1, gi + 0u);
        float n1 = noise_f(nk0, nk1, gi + 1u);
        float n2 = noise_f(nk0, nk1, gi + 2u);
        float n3 = noise_f(nk0, nk1, gi + 3u);
        float4 o;
        o.x = xv.x * mk[0] * n0;
        o.y = xv.y * mk[1] * n1;
        o.z = xv.z * mk[2] * n2;
        o.w = xv.w * mk[3] * n3;
        out[gi >> 2] = o;
    }
}

// ---------------- launch ------------------------------------------------------
extern "C" void kernel_launch(void* const* d_in, const int* in_sizes, int n_in,
                              void* d_out, int out_size) {
    const float* x   = (const float*)d_in[0];
    float* out       = (float*)d_out;
    float* maskout   = out + NX;          // output layout: [x (NX) | mask (NU)]

    // jax.random.key(42) -> (0,42); partitionable fold-like split:
    uint32_t mk0, mk1, nk0, nk1;
    tf2x32_i(0u, 42u, 0u, 0u, mk0, mk1);    // k_mask
    tf2x32_i(0u, 42u, 0u, 1u, nk0, nk1);    // k_noise

    k_init     <<<512, 256>>>();
    k_hist     <<<BSZ * SEG, 256>>>(mk0, mk1);
    k_scan     <<<1, 64>>>();
    k_collect  <<<(NU / 4) / 256, 256>>>();
    k_resolve  <<<BSZ, 256>>>();
    k_out_fused<<<(NU / 4) / 256, 256>>>((const float4*)x, (float4*)out,
                                         (float4*)maskout, nk0, nk1);
}